// round 2
// baseline (speedup 1.0000x reference)
#include <cuda_runtime.h>
#include <math.h>

typedef unsigned long long u64;

#define N_NODES 256
#define F_IN    128
#define F_OUT   64
#define BT_TOTAL 512

// dup'd A-tile: 64 k-values stored twice each (128 floats) + 4 pad -> stride 132
// rows differing by 4 -> 4*132 = 528 = 16 mod 32 -> distinct banks for the two
// row-groups a warp touches; 132*4B = 528B = 0 mod 16 -> float4 aligned rows.
#define SD_STRIDE 132

// ---- smem layout (float offsets) ----
#define OFF_SWH   0                     // sWh   [256][64]      16384
#define OFF_DUP   16384                 // sDup  [64][132]       8448  (h-dup / alpha-dup)
#define OFF_SW    (OFF_DUP + 8448)      // sW    [128][64]       8192
#define OFF_SWH1  (OFF_SW + 8192)       // 256
#define OFF_SWH2  (OFF_SWH1 + 256)      // 256
#define OFF_RMAX  (OFF_SWH2 + 256)      // 256
#define OFF_RINV  (OFF_RMAX + 256)      // 256
#define SMEM_FLOATS (OFF_RINV + 256)
#define SMEM_BYTES  (SMEM_FLOATS * 4)   // 136192 B

__device__ __forceinline__ void ffma2(u64& d, u64 a, u64 b) {
    asm("fma.rn.f32x2 %0, %1, %2, %0;" : "+l"(d) : "l"(a), "l"(b));
}
__device__ __forceinline__ void unpack2(float& lo, float& hi, u64 v) {
    asm("mov.b64 {%0, %1}, %2;" : "=f"(lo), "=f"(hi) : "l"(v));
}

// 64-row x 64-col tile GEMM step over 64 k-values.
// sAd: value-duplicated A tile [64 rows][2*64 k + pad], sB: row-major [64 k][64 cols].
// Thread computes 4 rows x 4 cols; packed over column pairs.
__device__ __forceinline__ void mma64(const float* __restrict__ sAd,
                                      const float* __restrict__ sB,
                                      int lr0, int c0,
                                      u64* __restrict__ acc01,
                                      u64* __restrict__ acc23)
{
    #pragma unroll 4
    for (int k0 = 0; k0 < 64; k0 += 2) {
        ulonglong2 b0 = *(const ulonglong2*)(sB + (k0 + 0) * F_OUT + c0);
        ulonglong2 b1 = *(const ulonglong2*)(sB + (k0 + 1) * F_OUT + c0);
        ulonglong2 a0 = *(const ulonglong2*)(sAd + (lr0 + 0) * SD_STRIDE + 2 * k0);
        ulonglong2 a1 = *(const ulonglong2*)(sAd + (lr0 + 1) * SD_STRIDE + 2 * k0);
        ulonglong2 a2 = *(const ulonglong2*)(sAd + (lr0 + 2) * SD_STRIDE + 2 * k0);
        ulonglong2 a3 = *(const ulonglong2*)(sAd + (lr0 + 3) * SD_STRIDE + 2 * k0);
        // k0
        ffma2(acc01[0], a0.x, b0.x); ffma2(acc23[0], a0.x, b0.y);
        ffma2(acc01[1], a1.x, b0.x); ffma2(acc23[1], a1.x, b0.y);
        ffma2(acc01[2], a2.x, b0.x); ffma2(acc23[2], a2.x, b0.y);
        ffma2(acc01[3], a3.x, b0.x); ffma2(acc23[3], a3.x, b0.y);
        // k0+1
        ffma2(acc01[0], a0.y, b1.x); ffma2(acc23[0], a0.y, b1.y);
        ffma2(acc01[1], a1.y, b1.x); ffma2(acc23[1], a1.y, b1.y);
        ffma2(acc01[2], a2.y, b1.x); ffma2(acc23[2], a2.y, b1.y);
        ffma2(acc01[3], a3.y, b1.x); ffma2(acc23[3], a3.y, b1.y);
    }
}

__global__ __launch_bounds__(256, 1)
void gat_fused_kernel(const float* __restrict__ h,
                      const float* __restrict__ W,
                      const float* __restrict__ a,
                      const float* __restrict__ adj,
                      float* __restrict__ out)
{
    extern __shared__ float smem[];
    float* sWh  = smem + OFF_SWH;
    float* sDup = smem + OFF_DUP;
    float* sW   = smem + OFF_SW;
    float* sWh1 = smem + OFF_SWH1;
    float* sWh2 = smem + OFF_SWH2;
    float* rmax = smem + OFF_RMAX;
    float* rinv = smem + OFF_RINV;

    const int tid  = threadIdx.x;
    const int bt   = blockIdx.x;
    const int lane = tid & 31;
    const int warp = tid >> 5;

    const int tc  = tid & 15;
    const int tr  = tid >> 4;
    const int c0  = tc * 4;
    const int lr0 = tr * 4;

    const float* hB = h + (size_t)bt * N_NODES * F_IN;

    // ---- load W into smem [128][64] row-major ----
    {
        const float4* Wsrc = reinterpret_cast<const float4*>(W);
        float4* Wdst = reinterpret_cast<float4*>(sW);
        #pragma unroll
        for (int idx = tid; idx < (F_IN * F_OUT) / 4; idx += 256)
            Wdst[idx] = Wsrc[idx];
    }

    float a1v[4], a2v[4];
    #pragma unroll
    for (int j = 0; j < 4; ++j) {
        a1v[j] = a[c0 + j];
        a2v[j] = a[F_OUT + c0 + j];
    }

    // ================= Phase 1: Wh = h @ W (+ Wh1/Wh2) =================
    for (int cb = 0; cb < N_NODES; cb += 64) {
        u64 acc01[4] = {0, 0, 0, 0};
        u64 acc23[4] = {0, 0, 0, 0};

        #pragma unroll
        for (int kp = 0; kp < 2; ++kp) {
            __syncthreads();  // previous reads of sDup done
            // fill sDup with value-duplicated h chunk: rows [cb,cb+64), k in [kp*64, kp*64+64)
            #pragma unroll
            for (int t = 0; t < 4; ++t) {
                int idx = tid + 256 * t;
                int r   = idx >> 4;       // 16 float4 per row
                int c4  = idx & 15;
                float4 v = *(const float4*)(hB + (size_t)(cb + r) * F_IN + kp * 64 + c4 * 4);
                float* d = sDup + r * SD_STRIDE + 8 * c4;
                *(float4*)(d)     = make_float4(v.x, v.x, v.y, v.y);
                *(float4*)(d + 4) = make_float4(v.z, v.z, v.w, v.w);
            }
            __syncthreads();
            mma64(sDup, sW + kp * 64 * F_OUT, lr0, c0, acc01, acc23);
        }

        // epilogue: unpack, write sWh tile + attention partials
        float af[4][4];
        #pragma unroll
        for (int i = 0; i < 4; ++i) {
            unpack2(af[i][0], af[i][1], acc01[i]);
            unpack2(af[i][2], af[i][3], acc23[i]);
        }
        float p1[4], p2[4];
        #pragma unroll
        for (int i = 0; i < 4; ++i) {
            int r = cb + lr0 + i;
            *(float4*)(&sWh[r * F_OUT + c0]) =
                make_float4(af[i][0], af[i][1], af[i][2], af[i][3]);
            p1[i] = af[i][0]*a1v[0] + af[i][1]*a1v[1] + af[i][2]*a1v[2] + af[i][3]*a1v[3];
            p2[i] = af[i][0]*a2v[0] + af[i][1]*a2v[1] + af[i][2]*a2v[2] + af[i][3]*a2v[3];
        }
        #pragma unroll
        for (int off = 8; off > 0; off >>= 1) {
            #pragma unroll
            for (int i = 0; i < 4; ++i) {
                p1[i] += __shfl_xor_sync(0xffffffffu, p1[i], off);
                p2[i] += __shfl_xor_sync(0xffffffffu, p2[i], off);
            }
        }
        if (tc == 0) {
            #pragma unroll
            for (int i = 0; i < 4; ++i) {
                sWh1[cb + lr0 + i] = p1[i];
                sWh2[cb + lr0 + i] = p2[i];
            }
        }
    }
    __syncthreads();

    // ================= Phase 2: per-row softmax max & 1/sum =================
    for (int i = warp; i < N_NODES; i += 8) {
        const float s = sWh1[i];
        const float* adjrow = adj + i * N_NODES;
        float vals[8];
        #pragma unroll
        for (int q = 0; q < 8; ++q) {
            int j = lane + 32 * q;
            float ad = __ldg(adjrow + j);
            float e = s + sWh2[j];
            e = e > 0.0f ? e : 0.01f * e;
            vals[q] = (ad > 0.0f) ? e : -3.0e38f;
        }
        float m = vals[0];
        #pragma unroll
        for (int q = 1; q < 8; ++q) m = fmaxf(m, vals[q]);
        #pragma unroll
        for (int off = 16; off > 0; off >>= 1)
            m = fmaxf(m, __shfl_xor_sync(0xffffffffu, m, off));
        float sum = 0.0f;
        #pragma unroll
        for (int q = 0; q < 8; ++q)
            sum += (vals[q] > -1.0e38f) ? __expf(vals[q] - m) : 0.0f;
        #pragma unroll
        for (int off = 16; off > 0; off >>= 1)
            sum += __shfl_xor_sync(0xffffffffu, sum, off);
        if (lane == 0) {
            rmax[i] = m;
            rinv[i] = 1.0f / sum;
        }
    }
    __syncthreads();

    // ================= Phase 3: h' = alpha @ Wh, ELU =================
    float* outB = out + (size_t)bt * N_NODES * F_OUT;
    for (int cb = 0; cb < N_NODES; cb += 64) {
        u64 acc01[4] = {0, 0, 0, 0};
        u64 acc23[4] = {0, 0, 0, 0};

        #pragma unroll
        for (int ks = 0; ks < 4; ++ks) {
            __syncthreads();  // previous reads of sDup done
            // fill sDup with duplicated alpha slice: rows [cb,cb+64), k = neighbors [ks*64, ks*64+64)
            #pragma unroll
            for (int t = 0; t < 8; ++t) {
                int r  = warp * 8 + t;
                int gi = cb + r;
                int j0 = ks * 64 + 2 * lane;
                float2 ad = *(const float2*)(adj + (size_t)gi * N_NODES + j0);
                float s   = sWh1[gi];
                float m   = rmax[gi];
                float inv = rinv[gi];
                float2 w2 = *(const float2*)(sWh2 + j0);
                float e0 = s + w2.x; e0 = e0 > 0.0f ? e0 : 0.01f * e0;
                float e1 = s + w2.y; e1 = e1 > 0.0f ? e1 : 0.01f * e1;
                float p0 = (ad.x > 0.0f) ? __expf(e0 - m) * inv : 0.0f;
                float p1v = (ad.y > 0.0f) ? __expf(e1 - m) * inv : 0.0f;
                *(float4*)(sDup + r * SD_STRIDE + 4 * lane) = make_float4(p0, p0, p1v, p1v);
            }
            __syncthreads();
            mma64(sDup, sWh + ks * 64 * F_OUT, lr0, c0, acc01, acc23);
        }

        // epilogue: ELU + store
        #pragma unroll
        for (int i = 0; i < 4; ++i) {
            int r = cb + lr0 + i;
            float x0, x1, x2, x3;
            unpack2(x0, x1, acc01[i]);
            unpack2(x2, x3, acc23[i]);
            float4 v;
            v.x = x0 > 0.0f ? x0 : expm1f(x0);
            v.y = x1 > 0.0f ? x1 : expm1f(x1);
            v.z = x2 > 0.0f ? x2 : expm1f(x2);
            v.w = x3 > 0.0f ? x3 : expm1f(x3);
            *(float4*)(&outB[(size_t)r * F_OUT + c0]) = v;
        }
    }
}

extern "C" void kernel_launch(void* const* d_in, const int* in_sizes, int n_in,
                              void* d_out, int out_size)
{
    const float* h   = (const float*)d_in[0];   // (8,64,256,128)
    const float* W   = (const float*)d_in[1];   // (128,64)
    const float* a   = (const float*)d_in[2];   // (128,1)
    const float* adj = (const float*)d_in[3];   // (256,256)
    float* out = (float*)d_out;                 // (8,64,256,64)

    cudaFuncSetAttribute(gat_fused_kernel,
                         cudaFuncAttributeMaxDynamicSharedMemorySize, SMEM_BYTES);
    gat_fused_kernel<<<BT_TOTAL, 256, SMEM_BYTES>>>(h, W, a, adj, out);
}

// round 3
// speedup vs baseline: 1.3068x; 1.3068x over previous
#include <cuda_runtime.h>
#include <math.h>

#define N_NODES 256
#define F_IN    128
#define F_OUT   64
#define BT_TOTAL 512
#define NTHREADS 512

// padded smem strides (floats): (4r + k) mod 32 bank pattern -> row-groups
// differing by 4 land 16 banks apart => conflict-free LDS.128 a-loads
#define SH_STRIDE 132
#define SA_STRIDE 260

// ---- dynamic smem layout (float offsets) ----
// sWh  [256][64]                  @ 0        (16384)
// region2                         @ 16384:
//   phase1: sH [128][132] (16896) then sW [128][64] (8192) = 25088
//   phase3: sA [128][260]                                   = 33280
// sWh1/sWh2/rmax/rinv [256] each  @ 49664
#define OFF_SWH   0
#define OFF_R2    16384
#define OFF_SW    (OFF_R2 + 16896)
#define OFF_SWH1  (OFF_R2 + 33280)
#define OFF_SWH2  (OFF_SWH1 + 256)
#define OFF_RMAX  (OFF_SWH2 + 256)
#define OFF_RINV  (OFF_RMAX + 256)
#define SMEM_FLOATS (OFF_RINV + 256)
#define SMEM_BYTES  (SMEM_FLOATS * 4)   // 202752 B

__global__ __launch_bounds__(NTHREADS, 1)
void gat_fused_kernel(const float* __restrict__ h,
                      const float* __restrict__ W,
                      const float* __restrict__ a,
                      const float* __restrict__ adj,
                      float* __restrict__ out)
{
    extern __shared__ float smem[];
    float* sWh  = smem + OFF_SWH;
    float* sH   = smem + OFF_R2;     // phase 1
    float* sW   = smem + OFF_SW;     // phase 1
    float* sA   = smem + OFF_R2;     // phase 3 (aliases sH+sW)
    float* sWh1 = smem + OFF_SWH1;
    float* sWh2 = smem + OFF_SWH2;
    float* rmax = smem + OFF_RMAX;
    float* rinv = smem + OFF_RINV;

    const int tid  = threadIdx.x;
    const int bt   = blockIdx.x;
    const int lane = tid & 31;
    const int warp = tid >> 5;       // 0..15

    // 16 col-groups x 32 row-groups, 4x4 register tile per thread
    const int tc  = tid & 15;
    const int tr  = tid >> 4;        // 0..31
    const int c0  = tc * 4;
    const int lr0 = tr * 4;          // 0..124

    const float* hB = h + (size_t)bt * N_NODES * F_IN;

    // ---- load W into smem [128][64] row-major ----
    {
        const float4* Wsrc = reinterpret_cast<const float4*>(W);
        float4* Wdst = reinterpret_cast<float4*>(sW);
        #pragma unroll
        for (int idx = tid; idx < (F_IN * F_OUT) / 4; idx += NTHREADS)
            Wdst[idx] = Wsrc[idx];
    }

    float a1v[4], a2v[4];
    #pragma unroll
    for (int j = 0; j < 4; ++j) {
        a1v[j] = a[c0 + j];
        a2v[j] = a[F_OUT + c0 + j];
    }

    // ================= Phase 1: Wh = h @ W (+ Wh1/Wh2 partials) =================
    for (int cb = 0; cb < N_NODES; cb += 128) {
        __syncthreads();   // previous chunk's sH readers done (1st iter: covers sW fill)
        // fill sH: 128 rows x 128 k (padded stride)
        #pragma unroll
        for (int t = 0; t < 8; ++t) {
            int idx = tid + NTHREADS * t;
            int r   = idx >> 5;          // 32 float4 per row
            int c4  = idx & 31;
            *reinterpret_cast<float4*>(&sH[r * SH_STRIDE + c4 * 4]) =
                *reinterpret_cast<const float4*>(hB + (size_t)(cb + r) * F_IN + c4 * 4);
        }
        __syncthreads();

        float acc[4][4] = {};
        #pragma unroll 4
        for (int k = 0; k < F_IN; ++k) {
            float4 bv = *reinterpret_cast<const float4*>(&sW[k * F_OUT + c0]);
            float av0 = sH[(lr0 + 0) * SH_STRIDE + k];
            float av1 = sH[(lr0 + 1) * SH_STRIDE + k];
            float av2 = sH[(lr0 + 2) * SH_STRIDE + k];
            float av3 = sH[(lr0 + 3) * SH_STRIDE + k];
            acc[0][0] += av0 * bv.x; acc[0][1] += av0 * bv.y; acc[0][2] += av0 * bv.z; acc[0][3] += av0 * bv.w;
            acc[1][0] += av1 * bv.x; acc[1][1] += av1 * bv.y; acc[1][2] += av1 * bv.z; acc[1][3] += av1 * bv.w;
            acc[2][0] += av2 * bv.x; acc[2][1] += av2 * bv.y; acc[2][2] += av2 * bv.z; acc[2][3] += av2 * bv.w;
            acc[3][0] += av3 * bv.x; acc[3][1] += av3 * bv.y; acc[3][2] += av3 * bv.z; acc[3][3] += av3 * bv.w;
        }

        // write Wh tile + per-row attention partials
        float p1[4], p2[4];
        #pragma unroll
        for (int i = 0; i < 4; ++i) {
            int r = cb + lr0 + i;
            *reinterpret_cast<float4*>(&sWh[r * F_OUT + c0]) =
                make_float4(acc[i][0], acc[i][1], acc[i][2], acc[i][3]);
            p1[i] = acc[i][0]*a1v[0] + acc[i][1]*a1v[1] + acc[i][2]*a1v[2] + acc[i][3]*a1v[3];
            p2[i] = acc[i][0]*a2v[0] + acc[i][1]*a2v[1] + acc[i][2]*a2v[2] + acc[i][3]*a2v[3];
        }
        #pragma unroll
        for (int off = 8; off > 0; off >>= 1) {
            #pragma unroll
            for (int i = 0; i < 4; ++i) {
                p1[i] += __shfl_xor_sync(0xffffffffu, p1[i], off);
                p2[i] += __shfl_xor_sync(0xffffffffu, p2[i], off);
            }
        }
        if (tc == 0) {
            #pragma unroll
            for (int i = 0; i < 4; ++i) {
                sWh1[cb + lr0 + i] = p1[i];
                sWh2[cb + lr0 + i] = p2[i];
            }
        }
    }
    __syncthreads();

    // ================= Phase 2: per-row softmax max & 1/sum =================
    for (int i = warp; i < N_NODES; i += 16) {
        const float s = sWh1[i];
        const float* adjrow = adj + i * N_NODES;
        float vals[8];
        #pragma unroll
        for (int q = 0; q < 8; ++q) {
            int j = lane + 32 * q;
            float ad = __ldg(adjrow + j);
            float e = s + sWh2[j];
            e = e > 0.0f ? e : 0.01f * e;
            vals[q] = (ad > 0.0f) ? e : -3.0e38f;
        }
        float m = vals[0];
        #pragma unroll
        for (int q = 1; q < 8; ++q) m = fmaxf(m, vals[q]);
        #pragma unroll
        for (int off = 16; off > 0; off >>= 1)
            m = fmaxf(m, __shfl_xor_sync(0xffffffffu, m, off));
        float sum = 0.0f;
        #pragma unroll
        for (int q = 0; q < 8; ++q)
            sum += (vals[q] > -1.0e38f) ? __expf(vals[q] - m) : 0.0f;
        #pragma unroll
        for (int off = 16; off > 0; off >>= 1)
            sum += __shfl_xor_sync(0xffffffffu, sum, off);
        if (lane == 0) {
            rmax[i] = m;
            rinv[i] = 1.0f / sum;
        }
    }
    __syncthreads();

    // ================= Phase 3: h' = alpha @ Wh, ELU =================
    float* outB = out + (size_t)bt * N_NODES * F_OUT;
    for (int cb = 0; cb < N_NODES; cb += 128) {
        // fill alpha tile sA[128][256] (recompute p_ij)
        #pragma unroll
        for (int t = 0; t < 64; ++t) {
            int idx = tid + NTHREADS * t;
            int r = idx >> 8;
            int j = idx & 255;
            int gi = cb + r;
            float ad = __ldg(adj + gi * N_NODES + j);
            float p = 0.0f;
            if (ad > 0.0f) {
                float e = sWh1[gi] + sWh2[j];
                e = e > 0.0f ? e : 0.01f * e;
                p = __expf(e - rmax[gi]) * rinv[gi];
            }
            sA[r * SA_STRIDE + j] = p;
        }
        __syncthreads();

        float acc[4][4] = {};
        #pragma unroll 4
        for (int k = 0; k < N_NODES; ++k) {
            float4 bv = *reinterpret_cast<const float4*>(&sWh[k * F_OUT + c0]);
            float av0 = sA[(lr0 + 0) * SA_STRIDE + k];
            float av1 = sA[(lr0 + 1) * SA_STRIDE + k];
            float av2 = sA[(lr0 + 2) * SA_STRIDE + k];
            float av3 = sA[(lr0 + 3) * SA_STRIDE + k];
            acc[0][0] += av0 * bv.x; acc[0][1] += av0 * bv.y; acc[0][2] += av0 * bv.z; acc[0][3] += av0 * bv.w;
            acc[1][0] += av1 * bv.x; acc[1][1] += av1 * bv.y; acc[1][2] += av1 * bv.z; acc[1][3] += av1 * bv.w;
            acc[2][0] += av2 * bv.x; acc[2][1] += av2 * bv.y; acc[2][2] += av2 * bv.z; acc[2][3] += av2 * bv.w;
            acc[3][0] += av3 * bv.x; acc[3][1] += av3 * bv.y; acc[3][2] += av3 * bv.z; acc[3][3] += av3 * bv.w;
        }

        // ELU + store
        #pragma unroll
        for (int i = 0; i < 4; ++i) {
            int r = cb + lr0 + i;
            float4 v;
            float x;
            x = acc[i][0]; v.x = x > 0.0f ? x : expm1f(x);
            x = acc[i][1]; v.y = x > 0.0f ? x : expm1f(x);
            x = acc[i][2]; v.z = x > 0.0f ? x : expm1f(x);
            x = acc[i][3]; v.w = x > 0.0f ? x : expm1f(x);
            *reinterpret_cast<float4*>(&outB[(size_t)r * F_OUT + c0]) = v;
        }
        __syncthreads();  // before next chunk overwrites sA
    }
}

extern "C" void kernel_launch(void* const* d_in, const int* in_sizes, int n_in,
                              void* d_out, int out_size)
{
    const float* h   = (const float*)d_in[0];   // (8,64,256,128)
    const float* W   = (const float*)d_in[1];   // (128,64)
    const float* a   = (const float*)d_in[2];   // (128,1)
    const float* adj = (const float*)d_in[3];   // (256,256)
    float* out = (float*)d_out;                 // (8,64,256,64)

    cudaFuncSetAttribute(gat_fused_kernel,
                         cudaFuncAttributeMaxDynamicSharedMemorySize, SMEM_BYTES);
    gat_fused_kernel<<<BT_TOTAL, NTHREADS, SMEM_BYTES>>>(h, W, a, adj, out);
}

// round 5
// speedup vs baseline: 2.0323x; 1.5552x over previous
#include <cuda_runtime.h>
#include <cuda_bf16.h>
#include <stdint.h>
#include <math.h>

#define N_NODES 256
#define F_IN    128
#define F_OUT   64
#define BT_TOTAL 512
#define NTHR    512

// bf16 element strides (row pitches): pitch*2 mod 128B == 16 -> conflict-free ldmatrix
#define A1_STR 136   // GEMM1 A tile [128][128]: 272B pitch
#define A2_STR 264   // GEMM2 A tile [128][256]: 528B pitch
#define BW_STR 72    // W  [128][64]: 144B pitch
#define B2_STR 72    // Wh [256][64]: 144B pitch

// ---- dynamic smem byte offsets ----
#define R_A_HI   0                      // 67584 (A2 tile size; GEMM1 uses first 34816)
#define R_A_LO   67584                  // 67584
#define G1_W_HI  (R_A_HI + 34816)       // 18432 (aliased into A region tail, GEMM1 only)
#define G1_W_LO  (R_A_LO + 34816)       // 18432
#define R_B2_HI  135168                 // 36864
#define R_B2_LO  172032                 // 36864
#define R_P1     208896                 // [2][256] f32 partial Wh1
#define R_P2     210944                 // [2][256] f32 partial Wh2
#define R_WH1    212992                 // [256] f32
#define R_WH2    214016
#define R_RMAX   215040
#define R_RINV   216064
#define R_AV     217088                 // a vector [128] f32
#define SM_TOTAL 217600

static __device__ __forceinline__ uint32_t smem_u32(const void* p) {
    uint32_t a;
    asm("{ .reg .u64 t; cvta.to.shared.u64 t, %1; cvt.u32.u64 %0, t; }" : "=r"(a) : "l"(p));
    return a;
}
static __device__ __forceinline__ void ldsm4(uint32_t& r0, uint32_t& r1, uint32_t& r2, uint32_t& r3, uint32_t addr) {
    asm volatile("ldmatrix.sync.aligned.m8n8.x4.shared.b16 {%0,%1,%2,%3}, [%4];"
                 : "=r"(r0), "=r"(r1), "=r"(r2), "=r"(r3) : "r"(addr));
}
static __device__ __forceinline__ void ldsm4t(uint32_t& r0, uint32_t& r1, uint32_t& r2, uint32_t& r3, uint32_t addr) {
    asm volatile("ldmatrix.sync.aligned.m8n8.x4.trans.shared.b16 {%0,%1,%2,%3}, [%4];"
                 : "=r"(r0), "=r"(r1), "=r"(r2), "=r"(r3) : "r"(addr));
}
static __device__ __forceinline__ void mma16816(float* c,
        uint32_t a0, uint32_t a1, uint32_t a2, uint32_t a3, uint32_t b0, uint32_t b1) {
    asm volatile("mma.sync.aligned.m16n8k16.row.col.f32.bf16.bf16.f32 "
                 "{%0,%1,%2,%3}, {%4,%5,%6,%7}, {%8,%9}, {%0,%1,%2,%3};"
                 : "+f"(c[0]), "+f"(c[1]), "+f"(c[2]), "+f"(c[3])
                 : "r"(a0), "r"(a1), "r"(a2), "r"(a3), "r"(b0), "r"(b1));
}
// split fp32 pair -> packed bf16x2 hi / lo words
static __device__ __forceinline__ void split2(float x, float y, uint32_t& hi, uint32_t& lo) {
    __nv_bfloat16 xh = __float2bfloat16(x), yh = __float2bfloat16(y);
    __nv_bfloat16 xl = __float2bfloat16(x - __bfloat162float(xh));
    __nv_bfloat16 yl = __float2bfloat16(y - __bfloat162float(yh));
    hi = ((uint32_t)__bfloat16_as_ushort(yh) << 16) | (uint32_t)__bfloat16_as_ushort(xh);
    lo = ((uint32_t)__bfloat16_as_ushort(yl) << 16) | (uint32_t)__bfloat16_as_ushort(xl);
}
static __device__ __forceinline__ void split4(float4 v, uint2& hi, uint2& lo) {
    split2(v.x, v.y, hi.x, lo.x);
    split2(v.z, v.w, hi.y, lo.y);
}

// warp-level 16m x 32n GEMM over Ksteps*16 k, 3-term bf16 split.
// aHi/aLo/bHi/bLo are per-lane ldmatrix base addresses (k=0).
// per k-step: A advances 32B (16 bf16), B advances 16 rows * bPitchB.
static __device__ __forceinline__ void warp_gemm(float acc[4][4],
        uint32_t aHi, uint32_t aLo, uint32_t bHi, uint32_t bLo,
        int Ksteps, int bPitchB)
{
    for (int k0 = 0; k0 < Ksteps; ++k0) {
        int ka = k0 * 32;
        int kb = k0 * 16 * bPitchB;
        uint32_t ah0, ah1, ah2, ah3, al0, al1, al2, al3;
        uint32_t bh[8], bl[8];
        ldsm4(ah0, ah1, ah2, ah3, aHi + ka);
        ldsm4(al0, al1, al2, al3, aLo + ka);
        ldsm4t(bh[0], bh[1], bh[2], bh[3], bHi + kb);
        ldsm4t(bh[4], bh[5], bh[6], bh[7], bHi + kb + 32);
        ldsm4t(bl[0], bl[1], bl[2], bl[3], bLo + kb);
        ldsm4t(bl[4], bl[5], bl[6], bl[7], bLo + kb + 32);
        #pragma unroll
        for (int j = 0; j < 4; ++j) {
            mma16816(acc[j], ah0, ah1, ah2, ah3, bh[2 * j], bh[2 * j + 1]);
            mma16816(acc[j], ah0, ah1, ah2, ah3, bl[2 * j], bl[2 * j + 1]);
            mma16816(acc[j], al0, al1, al2, al3, bh[2 * j], bh[2 * j + 1]);
        }
    }
}

__global__ __launch_bounds__(NTHR, 1)
void gat_mma_kernel(const float* __restrict__ h,
                    const float* __restrict__ W,
                    const float* __restrict__ a,
                    const float* __restrict__ adj,
                    float* __restrict__ out)
{
    extern __shared__ char smc[];
    const uint32_t sb = smem_u32(smc);
    float* sP1  = (float*)(smc + R_P1);
    float* sP2  = (float*)(smc + R_P2);
    float* wh1  = (float*)(smc + R_WH1);
    float* wh2  = (float*)(smc + R_WH2);
    float* rmax = (float*)(smc + R_RMAX);
    float* rinv = (float*)(smc + R_RINV);
    float* sav  = (float*)(smc + R_AV);

    const int tid  = threadIdx.x;
    const int wid  = tid >> 5;
    const int lane = tid & 31;
    const int bt   = blockIdx.x;

    const int mt = wid >> 1;           // m-tile 0..7 (16 rows each)
    const int nh = wid & 1;            // n-half 0..1 (32 cols each)
    const int mrow0 = mt * 16;
    const int ncol0 = nh * 32;
    const int q  = lane & 3;
    const int rw = lane >> 2;

    const float* hB = h + (size_t)bt * N_NODES * F_IN;

    // ---- one-time fills: W split + a vector ----
    {
        // W: 128x64 f32 -> 2048 float4
        for (int it = 0; it < 4; ++it) {
            int idx = tid + NTHR * it;
            int r = idx >> 4, c4 = idx & 15;
            float4 v = *(const float4*)(W + r * F_OUT + c4 * 4);
            uint2 hi, lo; split4(v, hi, lo);
            *(uint2*)(smc + G1_W_HI + r * 144 + c4 * 8) = hi;
            *(uint2*)(smc + G1_W_LO + r * 144 + c4 * 8) = lo;
        }
        if (tid < 128) sav[tid] = a[tid];
    }

    // per-lane ldmatrix bases (column parts)
    const uint32_t aLaneRow = (uint32_t)(lane & 15);
    const uint32_t aLaneCol = (uint32_t)((lane >> 4) * 8);

    // ================= Phase 1: Wh = h @ W =================
    for (int mc = 0; mc < 2; ++mc) {
        __syncthreads();   // protect sA region (first iter: also orders W fill)
        // fill A tile: h rows [mc*128, +128), split bf16, pitch A1_STR
        for (int it = 0; it < 8; ++it) {
            int idx = tid + NTHR * it;     // 4096 float4s
            int r = idx >> 5, c4 = idx & 31;
            float4 v = *(const float4*)(hB + (size_t)(mc * 128 + r) * F_IN + c4 * 4);
            uint2 hi, lo; split4(v, hi, lo);
            *(uint2*)(smc + R_A_HI + r * (A1_STR * 2) + c4 * 8) = hi;
            *(uint2*)(smc + R_A_LO + r * (A1_STR * 2) + c4 * 8) = lo;
        }
        __syncthreads();

        float acc[4][4] = {};
        uint32_t aHi = sb + R_A_HI + ((mrow0 + aLaneRow) * A1_STR + aLaneCol) * 2;
        uint32_t aLo = sb + R_A_LO + ((mrow0 + aLaneRow) * A1_STR + aLaneCol) * 2;
        uint32_t bHi = sb + G1_W_HI + (aLaneRow * BW_STR + ncol0 + aLaneCol) * 2;
        uint32_t bLo = sb + G1_W_LO + (aLaneRow * BW_STR + ncol0 + aLaneCol) * 2;
        warp_gemm(acc, aHi, aLo, bHi, bLo, F_IN / 16, BW_STR * 2);

        // epilogue: attention partials + Wh -> split bf16 into sB2
        float p1l = 0.f, p1h = 0.f, p2l = 0.f, p2h = 0.f;
        #pragma unroll
        for (int j = 0; j < 4; ++j) {
            int col = ncol0 + 8 * j + 2 * q;
            float a10 = sav[col], a11 = sav[col + 1];
            float a20 = sav[64 + col], a21 = sav[64 + col + 1];
            p1l += acc[j][0] * a10 + acc[j][1] * a11;
            p1h += acc[j][2] * a10 + acc[j][3] * a11;
            p2l += acc[j][0] * a20 + acc[j][1] * a21;
            p2h += acc[j][2] * a20 + acc[j][3] * a21;
        }
        #pragma unroll
        for (int off = 1; off <= 2; off <<= 1) {
            p1l += __shfl_xor_sync(0xffffffffu, p1l, off);
            p1h += __shfl_xor_sync(0xffffffffu, p1h, off);
            p2l += __shfl_xor_sync(0xffffffffu, p2l, off);
            p2h += __shfl_xor_sync(0xffffffffu, p2h, off);
        }
        int row0 = mc * 128 + mrow0 + rw;
        if (q == 0) {
            sP1[nh * 256 + row0]     = p1l;
            sP1[nh * 256 + row0 + 8] = p1h;
            sP2[nh * 256 + row0]     = p2l;
            sP2[nh * 256 + row0 + 8] = p2h;
        }
        #pragma unroll
        for (int j = 0; j < 4; ++j) {
            int col = ncol0 + 8 * j + 2 * q;
            uint32_t hi, lo;
            split2(acc[j][0], acc[j][1], hi, lo);
            *(uint32_t*)(smc + R_B2_HI + (row0 * B2_STR + col) * 2) = hi;
            *(uint32_t*)(smc + R_B2_LO + (row0 * B2_STR + col) * 2) = lo;
            split2(acc[j][2], acc[j][3], hi, lo);
            *(uint32_t*)(smc + R_B2_HI + ((row0 + 8) * B2_STR + col) * 2) = hi;
            *(uint32_t*)(smc + R_B2_LO + ((row0 + 8) * B2_STR + col) * 2) = lo;
        }
    }
    __syncthreads();

    // ---- combine Wh1/Wh2 partials ----
    if (tid < 256) {
        wh1[tid] = sP1[tid] + sP1[256 + tid];
        wh2[tid] = sP2[tid] + sP2[256 + tid];
    }
    __syncthreads();

    // ================= Phase 2: softmax stats =================
    for (int i = wid; i < N_NODES; i += 16) {
        const float s = wh1[i];
        const float* adjrow = adj + (size_t)i * N_NODES;
        float vals[8];
        #pragma unroll
        for (int p = 0; p < 8; ++p) {
            int j = lane + 32 * p;
            float ad = __ldg(adjrow + j);
            float e = s + wh2[j];
            e = e > 0.0f ? e : 0.01f * e;
            vals[p] = (ad > 0.0f) ? e : -3.0e38f;
        }
        float m = vals[0];
        #pragma unroll
        for (int p = 1; p < 8; ++p) m = fmaxf(m, vals[p]);
        #pragma unroll
        for (int off = 16; off > 0; off >>= 1)
            m = fmaxf(m, __shfl_xor_sync(0xffffffffu, m, off));
        float sum = 0.0f;
        #pragma unroll
        for (int p = 0; p < 8; ++p)
            sum += (vals[p] > -1.0e38f) ? __expf(vals[p] - m) : 0.0f;
        #pragma unroll
        for (int off = 16; off > 0; off >>= 1)
            sum += __shfl_xor_sync(0xffffffffu, sum, off);
        if (lane == 0) { rmax[i] = m; rinv[i] = 1.0f / sum; }
    }

    // ================= Phase 3: h' = alpha @ Wh, ELU =================
    float* outB = out + (size_t)bt * N_NODES * F_OUT;
    for (int mc = 0; mc < 2; ++mc) {
        __syncthreads();   // previous readers of sA done (also orders phase2 stats on 1st iter)
        // fill alpha tile [128 m][256 k], split bf16, pitch A2_STR
        for (int it = 0; it < 16; ++it) {
            int idx = tid + NTHR * it;   // 8192 float4s
            int r = idx >> 6, c4 = idx & 63;
            int gi = mc * 128 + r;
            float4 ad = *(const float4*)(adj + (size_t)gi * N_NODES + c4 * 4);
            float s1 = wh1[gi], mm = rmax[gi], inv = rinv[gi];
            int j0 = c4 * 4;
            float pv[4];
            #pragma unroll
            for (int c = 0; c < 4; ++c) {
                float e = s1 + wh2[j0 + c];
                e = e > 0.0f ? e : 0.01f * e;
                float adv = (c == 0) ? ad.x : (c == 1) ? ad.y : (c == 2) ? ad.z : ad.w;
                pv[c] = (adv > 0.0f) ? __expf(e - mm) * inv : 0.0f;
            }
            uint2 hi, lo;
            split4(make_float4(pv[0], pv[1], pv[2], pv[3]), hi, lo);
            *(uint2*)(smc + R_A_HI + r * (A2_STR * 2) + c4 * 8) = hi;
            *(uint2*)(smc + R_A_LO + r * (A2_STR * 2) + c4 * 8) = lo;
        }
        __syncthreads();

        float acc[4][4] = {};
        uint32_t aHi = sb + R_A_HI + ((mrow0 + aLaneRow) * A2_STR + aLaneCol) * 2;
        uint32_t aLo = sb + R_A_LO + ((mrow0 + aLaneRow) * A2_STR + aLaneCol) * 2;
        uint32_t bHi = sb + R_B2_HI + (aLaneRow * B2_STR + ncol0 + aLaneCol) * 2;
        uint32_t bLo = sb + R_B2_LO + (aLaneRow * B2_STR + ncol0 + aLaneCol) * 2;
        warp_gemm(acc, aHi, aLo, bHi, bLo, N_NODES / 16, B2_STR * 2);

        // epilogue: ELU + store
        int row0 = mc * 128 + mrow0 + rw;
        #pragma unroll
        for (int j = 0; j < 4; ++j) {
            int col = ncol0 + 8 * j + 2 * q;
            float x0 = acc[j][0], x1 = acc[j][1], x2 = acc[j][2], x3 = acc[j][3];
            float2 v0, v1;
            v0.x = x0 > 0.0f ? x0 : expm1f(x0);
            v0.y = x1 > 0.0f ? x1 : expm1f(x1);
            v1.x = x2 > 0.0f ? x2 : expm1f(x2);
            v1.y = x3 > 0.0f ? x3 : expm1f(x3);
            *(float2*)(outB + (size_t)row0 * F_OUT + col)       = v0;
            *(float2*)(outB + (size_t)(row0 + 8) * F_OUT + col) = v1;
        }
    }
}

extern "C" void kernel_launch(void* const* d_in, const int* in_sizes, int n_in,
                              void* d_out, int out_size)
{
    const float* h   = (const float*)d_in[0];   // (8,64,256,128)
    const float* W   = (const float*)d_in[1];   // (128,64)
    const float* a   = (const float*)d_in[2];   // (128,1)
    const float* adj = (const float*)d_in[3];   // (256,256)
    float* out = (float*)d_out;                 // (8,64,256,64)

    cudaFuncSetAttribute(gat_mma_kernel,
                         cudaFuncAttributeMaxDynamicSharedMemorySize, SM_TOTAL);
    gat_mma_kernel<<<BT_TOTAL, NTHR, SM_TOTAL>>>(h, W, a, adj, out);
}

// round 6
// speedup vs baseline: 2.1499x; 1.0579x over previous
#include <cuda_runtime.h>
#include <cuda_bf16.h>
#include <stdint.h>
#include <math.h>

#define N_NODES 256
#define F_IN    128
#define F_OUT   64
#define BT_TOTAL 512
#define NTHR    512

// bf16 element strides (row pitches): pitch*2 mod 128B == 16 -> conflict-free ldmatrix
#define A1_STR 136   // GEMM1 A tile [128][128]: 272B pitch
#define A2_STR 264   // GEMM2 A tile [128][256]: 528B pitch
#define BW_STR 72    // W  [128][64]: 144B pitch
#define B2_STR 72    // Wh [256][64]: 144B pitch

// ---- dynamic smem byte offsets ----
#define R_A_HI   0                      // 67584 (A2 tile size; GEMM1 uses first 34816)
#define R_A_LO   67584                  // 67584
#define G1_W_HI  (R_A_HI + 34816)       // 18432 (aliased into A region tail, GEMM1 only)
#define G1_W_LO  (R_A_LO + 34816)       // 18432
#define R_B2_HI  135168                 // 36864
#define R_B2_LO  172032                 // 36864
#define R_P1     208896                 // [2][256] f32 partial Wh1
#define R_P2     210944                 // [2][256] f32 partial Wh2
#define R_WH1    212992                 // [256] f32
#define R_WH2    214016
#define R_RMAX   215040
#define R_RINV   216064
#define R_AV     217088                 // a vector [128] f32
#define SM_TOTAL 217600

static __device__ __forceinline__ uint32_t smem_u32(const void* p) {
    uint32_t a;
    asm("{ .reg .u64 t; cvta.to.shared.u64 t, %1; cvt.u32.u64 %0, t; }" : "=r"(a) : "l"(p));
    return a;
}
static __device__ __forceinline__ void ldsm4(uint32_t& r0, uint32_t& r1, uint32_t& r2, uint32_t& r3, uint32_t addr) {
    asm volatile("ldmatrix.sync.aligned.m8n8.x4.shared.b16 {%0,%1,%2,%3}, [%4];"
                 : "=r"(r0), "=r"(r1), "=r"(r2), "=r"(r3) : "r"(addr));
}
static __device__ __forceinline__ void ldsm4t(uint32_t& r0, uint32_t& r1, uint32_t& r2, uint32_t& r3, uint32_t addr) {
    asm volatile("ldmatrix.sync.aligned.m8n8.x4.trans.shared.b16 {%0,%1,%2,%3}, [%4];"
                 : "=r"(r0), "=r"(r1), "=r"(r2), "=r"(r3) : "r"(addr));
}
static __device__ __forceinline__ void mma16816(float* c,
        uint32_t a0, uint32_t a1, uint32_t a2, uint32_t a3, uint32_t b0, uint32_t b1) {
    asm volatile("mma.sync.aligned.m16n8k16.row.col.f32.bf16.bf16.f32 "
                 "{%0,%1,%2,%3}, {%4,%5,%6,%7}, {%8,%9}, {%0,%1,%2,%3};"
                 : "+f"(c[0]), "+f"(c[1]), "+f"(c[2]), "+f"(c[3])
                 : "r"(a0), "r"(a1), "r"(a2), "r"(a3), "r"(b0), "r"(b1));
}
// split fp32 pair -> packed bf16x2 hi / lo words
static __device__ __forceinline__ void split2(float x, float y, uint32_t& hi, uint32_t& lo) {
    __nv_bfloat16 xh = __float2bfloat16(x), yh = __float2bfloat16(y);
    __nv_bfloat16 xl = __float2bfloat16(x - __bfloat162float(xh));
    __nv_bfloat16 yl = __float2bfloat16(y - __bfloat162float(yh));
    hi = ((uint32_t)__bfloat16_as_ushort(yh) << 16) | (uint32_t)__bfloat16_as_ushort(xh);
    lo = ((uint32_t)__bfloat16_as_ushort(yl) << 16) | (uint32_t)__bfloat16_as_ushort(xl);
}
static __device__ __forceinline__ void split4(float4 v, uint2& hi, uint2& lo) {
    split2(v.x, v.y, hi.x, lo.x);
    split2(v.z, v.w, hi.y, lo.y);
}

// warp-level 16m x 32n GEMM over KSTEPS*16 k, 3-term bf16 split.
// Fully unrolled + double-buffered fragments: LDSMs for k+1 issue before MMAs
// for k, giving the scheduler independent work to hide LDS latency.
template<int KSTEPS, int BPITCH>
static __device__ __forceinline__ void warp_gemm(float acc[4][4],
        uint32_t aHi, uint32_t aLo, uint32_t bHi, uint32_t bLo)
{
    uint32_t ah[2][4], al[2][4], bh[2][8], bl[2][8];
    // preload k = 0
    ldsm4(ah[0][0], ah[0][1], ah[0][2], ah[0][3], aHi);
    ldsm4(al[0][0], al[0][1], al[0][2], al[0][3], aLo);
    ldsm4t(bh[0][0], bh[0][1], bh[0][2], bh[0][3], bHi);
    ldsm4t(bh[0][4], bh[0][5], bh[0][6], bh[0][7], bHi + 32);
    ldsm4t(bl[0][0], bl[0][1], bl[0][2], bl[0][3], bLo);
    ldsm4t(bl[0][4], bl[0][5], bl[0][6], bl[0][7], bLo + 32);
    #pragma unroll
    for (int k0 = 0; k0 < KSTEPS; ++k0) {
        const int cur = k0 & 1, nxt = cur ^ 1;
        if (k0 + 1 < KSTEPS) {
            const int ka = (k0 + 1) * 32;
            const int kb = (k0 + 1) * 16 * BPITCH;
            ldsm4(ah[nxt][0], ah[nxt][1], ah[nxt][2], ah[nxt][3], aHi + ka);
            ldsm4(al[nxt][0], al[nxt][1], al[nxt][2], al[nxt][3], aLo + ka);
            ldsm4t(bh[nxt][0], bh[nxt][1], bh[nxt][2], bh[nxt][3], bHi + kb);
            ldsm4t(bh[nxt][4], bh[nxt][5], bh[nxt][6], bh[nxt][7], bHi + kb + 32);
            ldsm4t(bl[nxt][0], bl[nxt][1], bl[nxt][2], bl[nxt][3], bLo + kb);
            ldsm4t(bl[nxt][4], bl[nxt][5], bl[nxt][6], bl[nxt][7], bLo + kb + 32);
        }
        #pragma unroll
        for (int j = 0; j < 4; ++j) {
            mma16816(acc[j], ah[cur][0], ah[cur][1], ah[cur][2], ah[cur][3], bh[cur][2*j], bh[cur][2*j+1]);
            mma16816(acc[j], ah[cur][0], ah[cur][1], ah[cur][2], ah[cur][3], bl[cur][2*j], bl[cur][2*j+1]);
            mma16816(acc[j], al[cur][0], al[cur][1], al[cur][2], al[cur][3], bh[cur][2*j], bh[cur][2*j+1]);
        }
    }
}

__global__ __launch_bounds__(NTHR, 1)
void gat_mma_kernel(const float* __restrict__ h,
                    const float* __restrict__ W,
                    const float* __restrict__ a,
                    const float* __restrict__ adj,
                    float* __restrict__ out)
{
    extern __shared__ char smc[];
    const uint32_t sb = smem_u32(smc);
    float* sP1  = (float*)(smc + R_P1);
    float* sP2  = (float*)(smc + R_P2);
    float* wh1  = (float*)(smc + R_WH1);
    float* wh2  = (float*)(smc + R_WH2);
    float* rmax = (float*)(smc + R_RMAX);
    float* rinv = (float*)(smc + R_RINV);
    float* sav  = (float*)(smc + R_AV);

    const int tid  = threadIdx.x;
    const int wid  = tid >> 5;
    const int lane = tid & 31;
    const int bt   = blockIdx.x;

    const int mt = wid >> 1;           // m-tile 0..7 (16 rows each)
    const int nh = wid & 1;            // n-half 0..1 (32 cols each)
    const int mrow0 = mt * 16;
    const int ncol0 = nh * 32;
    const int q  = lane & 3;
    const int rw = lane >> 2;

    const float* hB = h + (size_t)bt * N_NODES * F_IN;

    // ---- one-time fills: W split + a vector ----
    {
        #pragma unroll
        for (int it = 0; it < 4; ++it) {
            int idx = tid + NTHR * it;
            int r = idx >> 4, c4 = idx & 15;
            float4 v = *(const float4*)(W + r * F_OUT + c4 * 4);
            uint2 hi, lo; split4(v, hi, lo);
            *(uint2*)(smc + G1_W_HI + r * 144 + c4 * 8) = hi;
            *(uint2*)(smc + G1_W_LO + r * 144 + c4 * 8) = lo;
        }
        if (tid < 128) sav[tid] = a[tid];
    }

    // per-lane ldmatrix bases (column parts)
    const uint32_t aLaneRow = (uint32_t)(lane & 15);
    const uint32_t aLaneCol = (uint32_t)((lane >> 4) * 8);

    // ================= Phase 1: Wh = h @ W =================
    for (int mc = 0; mc < 2; ++mc) {
        __syncthreads();   // protect sA region (first iter: also orders W fill)
        // fill A tile: h rows [mc*128, +128), split bf16, pitch A1_STR
        #pragma unroll 2
        for (int it = 0; it < 8; ++it) {
            int idx = tid + NTHR * it;     // 4096 float4s
            int r = idx >> 5, c4 = idx & 31;
            float4 v = *(const float4*)(hB + (size_t)(mc * 128 + r) * F_IN + c4 * 4);
            uint2 hi, lo; split4(v, hi, lo);
            *(uint2*)(smc + R_A_HI + r * (A1_STR * 2) + c4 * 8) = hi;
            *(uint2*)(smc + R_A_LO + r * (A1_STR * 2) + c4 * 8) = lo;
        }
        __syncthreads();

        float acc[4][4] = {};
        uint32_t aHi = sb + R_A_HI + ((mrow0 + aLaneRow) * A1_STR + aLaneCol) * 2;
        uint32_t aLo = sb + R_A_LO + ((mrow0 + aLaneRow) * A1_STR + aLaneCol) * 2;
        uint32_t bHi = sb + G1_W_HI + (aLaneRow * BW_STR + ncol0 + aLaneCol) * 2;
        uint32_t bLo = sb + G1_W_LO + (aLaneRow * BW_STR + ncol0 + aLaneCol) * 2;
        warp_gemm<F_IN / 16, BW_STR * 2>(acc, aHi, aLo, bHi, bLo);

        // epilogue: attention partials + Wh -> split bf16 into sB2
        float p1l = 0.f, p1h = 0.f, p2l = 0.f, p2h = 0.f;
        #pragma unroll
        for (int j = 0; j < 4; ++j) {
            int col = ncol0 + 8 * j + 2 * q;
            float a10 = sav[col], a11 = sav[col + 1];
            float a20 = sav[64 + col], a21 = sav[64 + col + 1];
            p1l += acc[j][0] * a10 + acc[j][1] * a11;
            p1h += acc[j][2] * a10 + acc[j][3] * a11;
            p2l += acc[j][0] * a20 + acc[j][1] * a21;
            p2h += acc[j][2] * a20 + acc[j][3] * a21;
        }
        #pragma unroll
        for (int off = 1; off <= 2; off <<= 1) {
            p1l += __shfl_xor_sync(0xffffffffu, p1l, off);
            p1h += __shfl_xor_sync(0xffffffffu, p1h, off);
            p2l += __shfl_xor_sync(0xffffffffu, p2l, off);
            p2h += __shfl_xor_sync(0xffffffffu, p2h, off);
        }
        int row0 = mc * 128 + mrow0 + rw;
        if (q == 0) {
            sP1[nh * 256 + row0]     = p1l;
            sP1[nh * 256 + row0 + 8] = p1h;
            sP2[nh * 256 + row0]     = p2l;
            sP2[nh * 256 + row0 + 8] = p2h;
        }
        #pragma unroll
        for (int j = 0; j < 4; ++j) {
            int col = ncol0 + 8 * j + 2 * q;
            uint32_t hi, lo;
            split2(acc[j][0], acc[j][1], hi, lo);
            *(uint32_t*)(smc + R_B2_HI + (row0 * B2_STR + col) * 2) = hi;
            *(uint32_t*)(smc + R_B2_LO + (row0 * B2_STR + col) * 2) = lo;
            split2(acc[j][2], acc[j][3], hi, lo);
            *(uint32_t*)(smc + R_B2_HI + ((row0 + 8) * B2_STR + col) * 2) = hi;
            *(uint32_t*)(smc + R_B2_LO + ((row0 + 8) * B2_STR + col) * 2) = lo;
        }
    }
    __syncthreads();

    // ---- combine Wh1/Wh2 partials ----
    if (tid < 256) {
        wh1[tid] = sP1[tid] + sP1[256 + tid];
        wh2[tid] = sP2[tid] + sP2[256 + tid];
    }
    __syncthreads();

    // ================= Phase 2: softmax stats =================
    for (int i = wid; i < N_NODES; i += 16) {
        const float s = wh1[i];
        const float* adjrow = adj + (size_t)i * N_NODES;
        float vals[8];
        #pragma unroll
        for (int p = 0; p < 8; ++p) {
            int j = lane + 32 * p;
            float ad = __ldg(adjrow + j);
            float e = s + wh2[j];
            e = e > 0.0f ? e : 0.01f * e;
            vals[p] = (ad > 0.0f) ? e : -3.0e38f;
        }
        float m = vals[0];
        #pragma unroll
        for (int p = 1; p < 8; ++p) m = fmaxf(m, vals[p]);
        #pragma unroll
        for (int off = 16; off > 0; off >>= 1)
            m = fmaxf(m, __shfl_xor_sync(0xffffffffu, m, off));
        float sum = 0.0f;
        #pragma unroll
        for (int p = 0; p < 8; ++p)
            sum += (vals[p] > -1.0e38f) ? __expf(vals[p] - m) : 0.0f;
        #pragma unroll
        for (int off = 16; off > 0; off >>= 1)
            sum += __shfl_xor_sync(0xffffffffu, sum, off);
        if (lane == 0) { rmax[i] = m; rinv[i] = 1.0f / sum; }
    }

    // ================= Phase 3: h' = alpha @ Wh, ELU =================
    float* outB = out + (size_t)bt * N_NODES * F_OUT;
    for (int mc = 0; mc < 2; ++mc) {
        __syncthreads();   // previous readers of sA done (also orders phase2 stats on 1st iter)
        // fill alpha tile [128 m][256 k], split bf16, pitch A2_STR
        #pragma unroll 4
        for (int it = 0; it < 16; ++it) {
            int idx = tid + NTHR * it;   // 8192 float4s
            int r = idx >> 6, c4 = idx & 63;
            int gi = mc * 128 + r;
            float4 ad = *(const float4*)(adj + (size_t)gi * N_NODES + c4 * 4);
            float s1 = wh1[gi], mm = rmax[gi], inv = rinv[gi];
            int j0 = c4 * 4;
            float pv[4];
            #pragma unroll
            for (int c = 0; c < 4; ++c) {
                float e = s1 + wh2[j0 + c];
                e = e > 0.0f ? e : 0.01f * e;
                float adv = (c == 0) ? ad.x : (c == 1) ? ad.y : (c == 2) ? ad.z : ad.w;
                pv[c] = (adv > 0.0f) ? __expf(e - mm) * inv : 0.0f;
            }
            uint2 hi, lo;
            split4(make_float4(pv[0], pv[1], pv[2], pv[3]), hi, lo);
            *(uint2*)(smc + R_A_HI + r * (A2_STR * 2) + c4 * 8) = hi;
            *(uint2*)(smc + R_A_LO + r * (A2_STR * 2) + c4 * 8) = lo;
        }
        __syncthreads();

        float acc[4][4] = {};
        uint32_t aHi = sb + R_A_HI + ((mrow0 + aLaneRow) * A2_STR + aLaneCol) * 2;
        uint32_t aLo = sb + R_A_LO + ((mrow0 + aLaneRow) * A2_STR + aLaneCol) * 2;
        uint32_t bHi = sb + R_B2_HI + (aLaneRow * B2_STR + ncol0 + aLaneCol) * 2;
        uint32_t bLo = sb + R_B2_LO + (aLaneRow * B2_STR + ncol0 + aLaneCol) * 2;
        warp_gemm<N_NODES / 16, B2_STR * 2>(acc, aHi, aLo, bHi, bLo);

        // epilogue: ELU + store
        int row0 = mc * 128 + mrow0 + rw;
        #pragma unroll
        for (int j = 0; j < 4; ++j) {
            int col = ncol0 + 8 * j + 2 * q;
            float x0 = acc[j][0], x1 = acc[j][1], x2 = acc[j][2], x3 = acc[j][3];
            float2 v0, v1;
            v0.x = x0 > 0.0f ? x0 : expm1f(x0);
            v0.y = x1 > 0.0f ? x1 : expm1f(x1);
            v1.x = x2 > 0.0f ? x2 : expm1f(x2);
            v1.y = x3 > 0.0f ? x3 : expm1f(x3);
            *(float2*)(outB + (size_t)row0 * F_OUT + col)       = v0;
            *(float2*)(outB + (size_t)(row0 + 8) * F_OUT + col) = v1;
        }
    }
}

extern "C" void kernel_launch(void* const* d_in, const int* in_sizes, int n_in,
                              void* d_out, int out_size)
{
    const float* h   = (const float*)d_in[0];   // (8,64,256,128)
    const float* W   = (const float*)d_in[1];   // (128,64)
    const float* a   = (const float*)d_in[2];   // (128,1)
    const float* adj = (const float*)d_in[3];   // (256,256)
    float* out = (float*)d_out;                 // (8,64,256,64)

    cudaFuncSetAttribute(gat_mma_kernel,
                         cudaFuncAttributeMaxDynamicSharedMemorySize, SM_TOTAL);
    gat_mma_kernel<<<BT_TOTAL, NTHR, SM_TOTAL>>>(h, W, a, adj, out);
}

// round 7
// speedup vs baseline: 2.5265x; 1.1752x over previous
#include <cuda_runtime.h>
#include <cuda_bf16.h>
#include <stdint.h>
#include <math.h>

#define N_NODES 256
#define F_IN    128
#define F_OUT   64
#define BT_TOTAL 512
#define NTHR    512

// bf16 row pitch 72 elems (144B): 144 mod 128 = 16 -> conflict-free ldmatrix
#define PITCH   72

// ---- smem byte offsets ----
#define AB_SIZE  (128 * PITCH * 2)          // 18432 B per hi- or lo-block (A chunk [128][64])
#define R_AB     0                          // 4 blocks: (buf*2 + hl)*AB_SIZE
#define R_W_HI   (R_AB + 4 * AB_SIZE)       // W [128][72] bf16
#define R_W_LO   (R_W_HI + AB_SIZE)
#define R_B2_HI  (R_W_LO + AB_SIZE)         // Wh [256][72] bf16
#define R_B2_LO  (R_B2_HI + 36864)
#define R_P1     (R_B2_LO + 36864)          // [2][256] f32
#define R_P2     (R_P1 + 2048)
#define R_WH1    (R_P2 + 2048)
#define R_WH2    (R_WH1 + 1024)
#define R_ST4    (R_WH2 + 1024)             // [256] float4 (wh1, rmax, rinv, _)
#define R_AV     (R_ST4 + 4096)             // a vector [128] f32
#define SM_TOTAL (R_AV + 512)               // 196096 B

static __device__ __forceinline__ uint32_t smem_u32(const void* p) {
    uint32_t a;
    asm("{ .reg .u64 t; cvta.to.shared.u64 t, %1; cvt.u32.u64 %0, t; }" : "=r"(a) : "l"(p));
    return a;
}
static __device__ __forceinline__ void ldsm4(uint32_t& r0, uint32_t& r1, uint32_t& r2, uint32_t& r3, uint32_t addr) {
    asm volatile("ldmatrix.sync.aligned.m8n8.x4.shared.b16 {%0,%1,%2,%3}, [%4];"
                 : "=r"(r0), "=r"(r1), "=r"(r2), "=r"(r3) : "r"(addr));
}
static __device__ __forceinline__ void ldsm4t(uint32_t& r0, uint32_t& r1, uint32_t& r2, uint32_t& r3, uint32_t addr) {
    asm volatile("ldmatrix.sync.aligned.m8n8.x4.trans.shared.b16 {%0,%1,%2,%3}, [%4];"
                 : "=r"(r0), "=r"(r1), "=r"(r2), "=r"(r3) : "r"(addr));
}
static __device__ __forceinline__ void mma16816(float* c,
        uint32_t a0, uint32_t a1, uint32_t a2, uint32_t a3, uint32_t b0, uint32_t b1) {
    asm volatile("mma.sync.aligned.m16n8k16.row.col.f32.bf16.bf16.f32 "
                 "{%0,%1,%2,%3}, {%4,%5,%6,%7}, {%8,%9}, {%0,%1,%2,%3};"
                 : "+f"(c[0]), "+f"(c[1]), "+f"(c[2]), "+f"(c[3])
                 : "r"(a0), "r"(a1), "r"(a2), "r"(a3), "r"(b0), "r"(b1));
}
// packed split: hi word = {bf16(y), bf16(x)}, lo word = residuals
static __device__ __forceinline__ void split2(float x, float y, uint32_t& hi, uint32_t& lo) {
    asm("cvt.rn.bf16x2.f32 %0, %1, %2;" : "=r"(hi) : "f"(y), "f"(x));
    float rx = __uint_as_float(hi << 16);
    float ry = __uint_as_float(hi & 0xFFFF0000u);
    asm("cvt.rn.bf16x2.f32 %0, %1, %2;" : "=r"(lo) : "f"(y - ry), "f"(x - rx));
}
static __device__ __forceinline__ void split4(float4 v, uint2& hi, uint2& lo) {
    split2(v.x, v.y, hi.x, lo.x);
    split2(v.z, v.w, hi.y, lo.y);
}

// 4-kstep (64 k) warp GEMM chunk, 3-term bf16 split, double-buffered fragments
static __device__ __forceinline__ void gemm_chunk(float acc[4][4],
        uint32_t aHi, uint32_t aLo, uint32_t bHi, uint32_t bLo)
{
    uint32_t ah[2][4], al[2][4], bh[2][8], bl[2][8];
    ldsm4(ah[0][0], ah[0][1], ah[0][2], ah[0][3], aHi);
    ldsm4(al[0][0], al[0][1], al[0][2], al[0][3], aLo);
    ldsm4t(bh[0][0], bh[0][1], bh[0][2], bh[0][3], bHi);
    ldsm4t(bh[0][4], bh[0][5], bh[0][6], bh[0][7], bHi + 32);
    ldsm4t(bl[0][0], bl[0][1], bl[0][2], bl[0][3], bLo);
    ldsm4t(bl[0][4], bl[0][5], bl[0][6], bl[0][7], bLo + 32);
    #pragma unroll
    for (int k0 = 0; k0 < 4; ++k0) {
        const int cur = k0 & 1, nxt = cur ^ 1;
        if (k0 < 3) {
            const int ka = (k0 + 1) * 32;
            const int kb = (k0 + 1) * 16 * (PITCH * 2);
            ldsm4(ah[nxt][0], ah[nxt][1], ah[nxt][2], ah[nxt][3], aHi + ka);
            ldsm4(al[nxt][0], al[nxt][1], al[nxt][2], al[nxt][3], aLo + ka);
            ldsm4t(bh[nxt][0], bh[nxt][1], bh[nxt][2], bh[nxt][3], bHi + kb);
            ldsm4t(bh[nxt][4], bh[nxt][5], bh[nxt][6], bh[nxt][7], bHi + kb + 32);
            ldsm4t(bl[nxt][0], bl[nxt][1], bl[nxt][2], bl[nxt][3], bLo + kb);
            ldsm4t(bl[nxt][4], bl[nxt][5], bl[nxt][6], bl[nxt][7], bLo + kb + 32);
        }
        #pragma unroll
        for (int j = 0; j < 4; ++j) {
            mma16816(acc[j], ah[cur][0], ah[cur][1], ah[cur][2], ah[cur][3], bh[cur][2*j], bh[cur][2*j+1]);
            mma16816(acc[j], ah[cur][0], ah[cur][1], ah[cur][2], ah[cur][3], bl[cur][2*j], bl[cur][2*j+1]);
            mma16816(acc[j], al[cur][0], al[cur][1], al[cur][2], al[cur][3], bh[cur][2*j], bh[cur][2*j+1]);
        }
    }
}

__global__ __launch_bounds__(NTHR, 1)
void gat_mma_kernel(const float* __restrict__ h,
                    const float* __restrict__ W,
                    const float* __restrict__ a,
                    const float* __restrict__ adj,
                    float* __restrict__ out)
{
    extern __shared__ char smc[];
    const uint32_t sb = smem_u32(smc);
    float*  sP1 = (float*)(smc + R_P1);
    float*  sP2 = (float*)(smc + R_P2);
    float*  wh1 = (float*)(smc + R_WH1);
    float*  wh2 = (float*)(smc + R_WH2);
    float4* st4 = (float4*)(smc + R_ST4);
    float*  sav = (float*)(smc + R_AV);

    const int tid  = threadIdx.x;
    const int wid  = tid >> 5;
    const int lane = tid & 31;
    const int bt   = blockIdx.x;

    const int mt = wid >> 1;           // m-tile 0..7 (16 rows)
    const int nh = wid & 1;            // n-half 0..1 (32 cols)
    const int mrow0 = mt * 16;
    const int ncol0 = nh * 32;
    const int q  = lane & 3;
    const int rw = lane >> 2;

    const float* hB = h + (size_t)bt * N_NODES * F_IN;

    const uint32_t laneRow = (uint32_t)(lane & 15);
    const uint32_t laneCol = (uint32_t)((lane >> 4) * 8);
    const uint32_t aOffB = ((mrow0 + laneRow) * PITCH + laneCol) * 2;   // within A block
    const uint32_t bOffB = (laneRow * PITCH + ncol0 + laneCol) * 2;     // within B block (row 0)

    // fill-loop index decomposition (shared by all chunk fills): 2048 float4 per chunk
    int fr[4], fc4[4];
    #pragma unroll
    for (int it = 0; it < 4; ++it) {
        int idx = tid + NTHR * it;
        fr[it]  = idx >> 4;      // row 0..127
        fc4[it] = idx & 15;      // float4-col 0..15
    }

    // ---- one-time fills: W split + a vector ----
    #pragma unroll
    for (int it = 0; it < 4; ++it) {
        float4 v = *(const float4*)(W + fr[it] * F_OUT + fc4[it] * 4);
        uint2 hi, lo; split4(v, hi, lo);
        *(uint2*)(smc + R_W_HI + (fr[it] * PITCH + fc4[it] * 4) * 2) = hi;
        *(uint2*)(smc + R_W_LO + (fr[it] * PITCH + fc4[it] * 4) * 2) = lo;
    }
    if (tid < 128) sav[tid] = a[tid];

    // ================= Phase 1: Wh = h @ W (k-chunk pipelined) =================
    float4 reg[4];
    #pragma unroll
    for (int it = 0; it < 4; ++it)
        reg[it] = *(const float4*)(hB + (size_t)fr[it] * F_IN + fc4[it] * 4);   // (mc0,kc0)
    #pragma unroll
    for (int it = 0; it < 4; ++it) {
        uint2 hi, lo; split4(reg[it], hi, lo);
        *(uint2*)(smc + R_AB + (fr[it] * PITCH + fc4[it] * 4) * 2) = hi;
        *(uint2*)(smc + R_AB + AB_SIZE + (fr[it] * PITCH + fc4[it] * 4) * 2) = lo;
    }
    __syncthreads();

    int buf = 0;
    #pragma unroll
    for (int mc = 0; mc < 2; ++mc) {
        float acc[4][4] = {};
        #pragma unroll
        for (int kc = 0; kc < 2; ++kc) {
            const bool hn = !(mc == 1 && kc == 1);
            const int nmc = (kc == 1) ? mc + 1 : mc;
            const int nkc = kc ^ 1;
            if (hn) {
                #pragma unroll
                for (int it = 0; it < 4; ++it)
                    reg[it] = *(const float4*)(hB + (size_t)(nmc * 128 + fr[it]) * F_IN + nkc * 64 + fc4[it] * 4);
            }
            gemm_chunk(acc,
                sb + R_AB + (buf * 2) * AB_SIZE + aOffB,
                sb + R_AB + (buf * 2 + 1) * AB_SIZE + aOffB,
                sb + R_W_HI + (uint32_t)(kc * 64) * (PITCH * 2) + bOffB,
                sb + R_W_LO + (uint32_t)(kc * 64) * (PITCH * 2) + bOffB);
            if (hn) {
                const int nb = buf ^ 1;
                #pragma unroll
                for (int it = 0; it < 4; ++it) {
                    uint2 hi, lo; split4(reg[it], hi, lo);
                    *(uint2*)(smc + R_AB + (nb * 2) * AB_SIZE + (fr[it] * PITCH + fc4[it] * 4) * 2) = hi;
                    *(uint2*)(smc + R_AB + (nb * 2 + 1) * AB_SIZE + (fr[it] * PITCH + fc4[it] * 4) * 2) = lo;
                }
            }
            __syncthreads();
            buf ^= 1;
        }
        // ---- epilogue1: attention partials + Wh -> split bf16 into B2 ----
        float p1l = 0.f, p1h = 0.f, p2l = 0.f, p2h = 0.f;
        #pragma unroll
        for (int j = 0; j < 4; ++j) {
            int col = ncol0 + 8 * j + 2 * q;
            float a10 = sav[col], a11 = sav[col + 1];
            float a20 = sav[64 + col], a21 = sav[64 + col + 1];
            p1l += acc[j][0] * a10 + acc[j][1] * a11;
            p1h += acc[j][2] * a10 + acc[j][3] * a11;
            p2l += acc[j][0] * a20 + acc[j][1] * a21;
            p2h += acc[j][2] * a20 + acc[j][3] * a21;
        }
        #pragma unroll
        for (int off = 1; off <= 2; off <<= 1) {
            p1l += __shfl_xor_sync(0xffffffffu, p1l, off);
            p1h += __shfl_xor_sync(0xffffffffu, p1h, off);
            p2l += __shfl_xor_sync(0xffffffffu, p2l, off);
            p2h += __shfl_xor_sync(0xffffffffu, p2h, off);
        }
        int row0 = mc * 128 + mrow0 + rw;
        if (q == 0) {
            sP1[nh * 256 + row0]     = p1l;
            sP1[nh * 256 + row0 + 8] = p1h;
            sP2[nh * 256 + row0]     = p2l;
            sP2[nh * 256 + row0 + 8] = p2h;
        }
        #pragma unroll
        for (int j = 0; j < 4; ++j) {
            int col = ncol0 + 8 * j + 2 * q;
            uint32_t hi, lo;
            split2(acc[j][0], acc[j][1], hi, lo);
            *(uint32_t*)(smc + R_B2_HI + (row0 * PITCH + col) * 2) = hi;
            *(uint32_t*)(smc + R_B2_LO + (row0 * PITCH + col) * 2) = lo;
            split2(acc[j][2], acc[j][3], hi, lo);
            *(uint32_t*)(smc + R_B2_HI + ((row0 + 8) * PITCH + col) * 2) = hi;
            *(uint32_t*)(smc + R_B2_LO + ((row0 + 8) * PITCH + col) * 2) = lo;
        }
    }
    __syncthreads();

    // ---- combine Wh1/Wh2 partials ----
    if (tid < 256) {
        wh1[tid] = sP1[tid] + sP1[256 + tid];
        wh2[tid] = sP2[tid] + sP2[256 + tid];
    }
    __syncthreads();

    // ================= Phase 2: softmax stats =================
    for (int i = wid; i < N_NODES; i += 16) {
        const float s = wh1[i];
        const float4* adjrow = (const float4*)(adj + (size_t)i * N_NODES);
        float4 a0 = __ldg(adjrow + lane * 2);
        float4 a1 = __ldg(adjrow + lane * 2 + 1);
        float4 w0 = *(const float4*)(wh2 + lane * 8);
        float4 w1 = *(const float4*)(wh2 + lane * 8 + 4);
        float ad[8] = {a0.x, a0.y, a0.z, a0.w, a1.x, a1.y, a1.z, a1.w};
        float wv[8] = {w0.x, w0.y, w0.z, w0.w, w1.x, w1.y, w1.z, w1.w};
        float vals[8];
        #pragma unroll
        for (int p = 0; p < 8; ++p) {
            float e = s + wv[p];
            e = e > 0.0f ? e : 0.01f * e;
            vals[p] = (ad[p] > 0.0f) ? e : -3.0e38f;
        }
        float m = vals[0];
        #pragma unroll
        for (int p = 1; p < 8; ++p) m = fmaxf(m, vals[p]);
        #pragma unroll
        for (int off = 16; off > 0; off >>= 1)
            m = fmaxf(m, __shfl_xor_sync(0xffffffffu, m, off));
        float sum = 0.0f;
        #pragma unroll
        for (int p = 0; p < 8; ++p)
            sum += (vals[p] > -1.0e38f) ? __expf(vals[p] - m) : 0.0f;
        #pragma unroll
        for (int off = 16; off > 0; off >>= 1)
            sum += __shfl_xor_sync(0xffffffffu, sum, off);
        if (lane == 0) st4[i] = make_float4(s, m, 1.0f / sum, 0.0f);
    }
    __syncthreads();

    // ================= Phase 3: h' = alpha @ Wh (k-chunk pipelined) =================
    float* outB = out + (size_t)bt * N_NODES * F_OUT;
    // initial fill (mc0, kc0) -> buf (buf == 0 here)
    #pragma unroll
    for (int it = 0; it < 4; ++it)
        reg[it] = __ldg((const float4*)(adj + (size_t)fr[it] * N_NODES + fc4[it] * 4));
    #pragma unroll
    for (int it = 0; it < 4; ++it) {
        float4 st = st4[fr[it]];
        float4 w = *(const float4*)(wh2 + fc4[it] * 4);
        float4 pv;
        float e;
        e = st.x + w.x; e = e > 0.f ? e : 0.01f * e; pv.x = (reg[it].x > 0.f) ? __expf(e - st.y) * st.z : 0.f;
        e = st.x + w.y; e = e > 0.f ? e : 0.01f * e; pv.y = (reg[it].y > 0.f) ? __expf(e - st.y) * st.z : 0.f;
        e = st.x + w.z; e = e > 0.f ? e : 0.01f * e; pv.z = (reg[it].z > 0.f) ? __expf(e - st.y) * st.z : 0.f;
        e = st.x + w.w; e = e > 0.f ? e : 0.01f * e; pv.w = (reg[it].w > 0.f) ? __expf(e - st.y) * st.z : 0.f;
        uint2 hi, lo; split4(pv, hi, lo);
        *(uint2*)(smc + R_AB + (fr[it] * PITCH + fc4[it] * 4) * 2) = hi;
        *(uint2*)(smc + R_AB + AB_SIZE + (fr[it] * PITCH + fc4[it] * 4) * 2) = lo;
    }
    __syncthreads();

    #pragma unroll
    for (int mc = 0; mc < 2; ++mc) {
        float acc[4][4] = {};
        #pragma unroll
        for (int kc = 0; kc < 4; ++kc) {
            const bool hn = !(mc == 1 && kc == 3);
            const int nmc = (kc == 3) ? mc + 1 : mc;
            const int nkc = (kc + 1) & 3;
            if (hn) {
                #pragma unroll
                for (int it = 0; it < 4; ++it)
                    reg[it] = __ldg((const float4*)(adj + (size_t)(nmc * 128 + fr[it]) * N_NODES + nkc * 64 + fc4[it] * 4));
            }
            gemm_chunk(acc,
                sb + R_AB + (buf * 2) * AB_SIZE + aOffB,
                sb + R_AB + (buf * 2 + 1) * AB_SIZE + aOffB,
                sb + R_B2_HI + (uint32_t)(kc * 64) * (PITCH * 2) + bOffB,
                sb + R_B2_LO + (uint32_t)(kc * 64) * (PITCH * 2) + bOffB);
            if (hn) {
                const int nb = buf ^ 1;
                #pragma unroll
                for (int it = 0; it < 4; ++it) {
                    float4 st = st4[nmc * 128 + fr[it]];
                    float4 w = *(const float4*)(wh2 + nkc * 64 + fc4[it] * 4);
                    float4 pv;
                    float e;
                    e = st.x + w.x; e = e > 0.f ? e : 0.01f * e; pv.x = (reg[it].x > 0.f) ? __expf(e - st.y) * st.z : 0.f;
                    e = st.x + w.y; e = e > 0.f ? e : 0.01f * e; pv.y = (reg[it].y > 0.f) ? __expf(e - st.y) * st.z : 0.f;
                    e = st.x + w.z; e = e > 0.f ? e : 0.01f * e; pv.z = (reg[it].z > 0.f) ? __expf(e - st.y) * st.z : 0.f;
                    e = st.x + w.w; e = e > 0.f ? e : 0.01f * e; pv.w = (reg[it].w > 0.f) ? __expf(e - st.y) * st.z : 0.f;
                    uint2 hi, lo; split4(pv, hi, lo);
                    *(uint2*)(smc + R_AB + (nb * 2) * AB_SIZE + (fr[it] * PITCH + fc4[it] * 4) * 2) = hi;
                    *(uint2*)(smc + R_AB + (nb * 2 + 1) * AB_SIZE + (fr[it] * PITCH + fc4[it] * 4) * 2) = lo;
                }
            }
            __syncthreads();
            buf ^= 1;
        }
        // ---- epilogue3: ELU + store ----
        int row0 = mc * 128 + mrow0 + rw;
        #pragma unroll
        for (int j = 0; j < 4; ++j) {
            int col = ncol0 + 8 * j + 2 * q;
            float x0 = acc[j][0], x1 = acc[j][1], x2 = acc[j][2], x3 = acc[j][3];
            float2 v0, v1;
            v0.x = x0 > 0.0f ? x0 : expm1f(x0);
            v0.y = x1 > 0.0f ? x1 : expm1f(x1);
            v1.x = x2 > 0.0f ? x2 : expm1f(x2);
            v1.y = x3 > 0.0f ? x3 : expm1f(x3);
            *(float2*)(outB + (size_t)row0 * F_OUT + col)       = v0;
            *(float2*)(outB + (size_t)(row0 + 8) * F_OUT + col) = v1;
        }
    }
}

extern "C" void kernel_launch(void* const* d_in, const int* in_sizes, int n_in,
                              void* d_out, int out_size)
{
    const float* h   = (const float*)d_in[0];   // (8,64,256,128)
    const float* W   = (const float*)d_in[1];   // (128,64)
    const float* a   = (const float*)d_in[2];   // (128,1)
    const float* adj = (const float*)d_in[3];   // (256,256)
    float* out = (float*)d_out;                 // (8,64,256,64)

    cudaFuncSetAttribute(gat_mma_kernel,
                         cudaFuncAttributeMaxDynamicSharedMemorySize, SM_TOTAL);
    gat_mma_kernel<<<BT_TOTAL, NTHR, SM_TOTAL>>>(h, W, a, adj, out);
}